// round 15
// baseline (speedup 1.0000x reference)
#include <cuda_runtime.h>
#include <cuda_bf16.h>
#include <cstdint>
#include <float.h>
#include <math.h>

// Problem constants
#define NTOK   2048          // N = F*H*W = 2*32*32
#define INNER  512
#define QKVW   1536          // 3*INNER
#define HEADS  8
#define DHEAD  64
#define KDIM   512           // GEMM K for both GEMMs

// Scratch (device globals; no allocation allowed)
__device__ float g_qkv[NTOK * QKVW];
__device__ __nv_bfloat16 g_xhi[NTOK * INNER],    g_xlo[NTOK * INNER];
__device__ __nv_bfloat16 g_w1hiT[QKVW * INNER],  g_w1loT[QKVW * INNER];   // [N,K]
__device__ __nv_bfloat16 g_ahi[NTOK * INNER],    g_alo[NTOK * INNER];
__device__ __nv_bfloat16 g_w2hiT[INNER * INNER], g_w2loT[INNER * INNER];  // [N,K]
__device__ int g_nbr[NTOK * 128];   // compacted valid window rows per query
__device__ int g_cnt[NTOK];         // valid count per query

// ---------------------------------------------------------------------------
// Fused prep: split x (plain) + transpose-split w_qkv, w_out.
// ---------------------------------------------------------------------------
__device__ __forceinline__ void split_quad(const float* __restrict__ in,
                                           __nv_bfloat16* __restrict__ hi,
                                           __nv_bfloat16* __restrict__ lo,
                                           int base) {
    float4 v = *reinterpret_cast<const float4*>(in + base);
    float vv[4] = {v.x, v.y, v.z, v.w};
    unsigned short h[4], l[4];
#pragma unroll
    for (int j = 0; j < 4; j++) {
        __nv_bfloat16 hb = __float2bfloat16_rn(vv[j]);
        h[j] = __bfloat16_as_ushort(hb);
        l[j] = __bfloat16_as_ushort(__float2bfloat16_rn(vv[j] - __bfloat162float(hb)));
    }
    uint2 ho = make_uint2((uint32_t)h[0] | ((uint32_t)h[1] << 16),
                          (uint32_t)h[2] | ((uint32_t)h[3] << 16));
    uint2 lz = make_uint2((uint32_t)l[0] | ((uint32_t)l[1] << 16),
                          (uint32_t)l[2] | ((uint32_t)l[3] << 16));
    *reinterpret_cast<uint2*>(hi + base) = ho;
    *reinterpret_cast<uint2*>(lo + base) = lz;
}

__device__ __forceinline__ void tsplit_tile(const float* __restrict__ in,
                                            __nv_bfloat16* __restrict__ hiT,
                                            __nv_bfloat16* __restrict__ loT,
                                            int K, int N, int n0, int k0,
                                            float (*sm)[33]) {
    const int tx = threadIdx.x & 31, ty = threadIdx.x >> 5;
#pragma unroll
    for (int i = 0; i < 4; i++)
        sm[ty + i * 8][tx] = in[(size_t)(k0 + ty + i * 8) * N + n0 + tx];
    __syncthreads();
#pragma unroll
    for (int i = 0; i < 4; i++) {
        int nr = ty + i * 8;
        float v = sm[tx][nr];
        __nv_bfloat16 hb = __float2bfloat16_rn(v);
        hiT[(size_t)(n0 + nr) * K + k0 + tx] = hb;
        loT[(size_t)(n0 + nr) * K + k0 + tx] =
            __float2bfloat16_rn(v - __bfloat162float(hb));
    }
}

__global__ void __launch_bounds__(256)
prep_kernel(const float* __restrict__ x, const float* __restrict__ w1,
            const float* __restrict__ w2,
            __nv_bfloat16* __restrict__ xhi, __nv_bfloat16* __restrict__ xlo,
            __nv_bfloat16* __restrict__ w1hiT, __nv_bfloat16* __restrict__ w1loT,
            __nv_bfloat16* __restrict__ w2hiT, __nv_bfloat16* __restrict__ w2loT) {
    __shared__ float sm[32][33];
    const int b = blockIdx.x;
    if (b < 1024) {
        split_quad(x, xhi, xlo, (b * 256 + threadIdx.x) * 4);
    } else if (b < 1024 + 768) {
        const int bx = b - 1024;                   // 48 x 16 tiles
        tsplit_tile(w1, w1hiT, w1loT, KDIM, QKVW,
                    (bx % 48) * 32, (bx / 48) * 32, sm);
    } else {
        const int bx = b - 1792;                   // 16 x 16 tiles
        tsplit_tile(w2, w2hiT, w2loT, KDIM, INNER,
                    (bx % 16) * 32, (bx / 16) * 32, sm);
    }
}

// ---------------------------------------------------------------------------
// Neighbor-list builder: warp per query, ballot compaction.
// ---------------------------------------------------------------------------
__global__ void __launch_bounds__(256)
nbr_kernel(int* __restrict__ nbr, int* __restrict__ cnt) {
    const int qi   = blockIdx.x * 8 + (threadIdx.x >> 5);
    const int lane = threadIdx.x & 31;
    if (qi >= 2047) {
        if (qi == 2047 && lane == 0) cnt[qi] = 0;
        return;
    }
    const int f  = qi >> 10;
    const int yy = (qi >> 5) & 31;
    const int xx = qi & 31;
    int base = 0;
#pragma unroll
    for (int t = 0; t < 4; t++) {
        const int s = t * 32 + lane;   // slot 0 = BOS, 1..125 = stencil
        bool valid = false;
        int row = 0;
        if (s == 0) {
            valid = true;
        } else if (s <= 125) {
            const int jj = s - 1;
            const int df = jj / 25;
            const int rem = jj - df * 25;
            const int dh = rem / 5;
            const int dw = rem - dh * 5;
            const int nf = f + df - 2, nh = yy + dh - 2, nw = xx + dw - 2;
            const int nidx = (nf << 10) + (nh << 5) + nw;
            valid = ((unsigned)nf < 2u) && ((unsigned)nh < 32u) &&
                    ((unsigned)nw < 32u) && (nidx <= qi);
            row = nidx + 1;
        }
        const unsigned mask = __ballot_sync(0xffffffffu, valid);
        const int pos = base + __popc(mask & ((1u << lane) - 1u));
        if (valid) nbr[qi * 128 + pos] = row;
        base += __popc(mask);
    }
    if (lane == 0) cnt[qi] = base;
}

// ---------------------------------------------------------------------------
// bf16x3 shared-operand GEMM (R13 config), templated block tile.
// ---------------------------------------------------------------------------
__device__ __forceinline__ void mma_bf16(float* c, const uint32_t* a, const uint32_t* b) {
    asm volatile(
        "mma.sync.aligned.m16n8k16.row.col.f32.bf16.bf16.f32 "
        "{%0,%1,%2,%3}, {%4,%5,%6,%7}, {%8,%9}, {%0,%1,%2,%3};\n"
        : "+f"(c[0]), "+f"(c[1]), "+f"(c[2]), "+f"(c[3])
        : "r"(a[0]), "r"(a[1]), "r"(a[2]), "r"(a[3]), "r"(b[0]), "r"(b[1]));
}

__device__ __forceinline__ void ldsm_x4(uint32_t addr, uint32_t* r) {
    asm volatile("ldmatrix.sync.aligned.m8n8.x4.shared.b16 {%0,%1,%2,%3}, [%4];"
                 : "=r"(r[0]), "=r"(r[1]), "=r"(r[2]), "=r"(r[3]) : "r"(addr));
}

__device__ __forceinline__ uint32_t smem_u32(const void* p) {
    uint32_t a;
    asm("{ .reg .u64 t; cvta.to.shared.u64 t, %1; cvt.u32.u64 %0, t; }"
        : "=r"(a) : "l"(p));
    return a;
}

template <int BM, int BN, int S, int MB>
__global__ void __launch_bounds__(256, MB)
gemm_so_kernel(const __nv_bfloat16* __restrict__ Ahi,
               const __nv_bfloat16* __restrict__ Alo,
               const __nv_bfloat16* __restrict__ Bhi,
               const __nv_bfloat16* __restrict__ Blo,
               float* __restrict__ C, const float* __restrict__ bias, int N) {
    constexpr int K = KDIM;
    constexpr int AT = BM * 64;                  // one A tile bytes
    constexpr int BT = BN * 64;                  // one B tile bytes
    constexpr int STAGE = 2 * AT + 2 * BT;       // Ahi|Alo|Bhi|Blo
    constexpr int NCH = K / 32;                  // 16
    constexpr int WM = BM / 2, WN = BN / 4;
    constexpr int MT = WM / 16, NT = WN / 8, NP = NT / 2;
    constexpr int ACH = BM / 64;                 // A 16B-units per thread
    constexpr int BCH = BN / 64;                 // B 16B-units per thread

    extern __shared__ char dsm[];

    const int tid  = threadIdx.x;
    const int lane = tid & 31, wid = tid >> 5;
    const int gid  = lane >> 2, tig = lane & 3;
    const int wm   = wid >> 2,  wn  = wid & 3;
    const int bm   = blockIdx.y * BM, bn = blockIdx.x * BN;
    const uint32_t sbase = smem_u32(dsm);

    const int lrow = lane & 15;
    const int chi  = lane >> 4;
    const int sx   = (lrow >> 1) & 3;

    float acc[MT][NT][4];
#pragma unroll
    for (int i = 0; i < MT; i++)
#pragma unroll
        for (int j = 0; j < NT; j++)
#pragma unroll
            for (int q = 0; q < 4; q++) acc[i][j][q] = 0.0f;

#define PREFETCH(c)                                                            \
    {                                                                          \
        const uint32_t _sb = sbase + ((c) % S) * STAGE;                        \
        const int _kk = (c) * 32;                                              \
        _Pragma("unroll")                                                      \
        for (int _i = 0; _i < ACH; _i++) {                                     \
            const int _u = tid + _i * 256;                                     \
            const int _r = _u >> 2, _c = _u & 3;                               \
            const uint32_t _d = _sb + _r * 64 + ((_c ^ ((_r >> 1) & 3)) << 4); \
            const size_t _o = (size_t)(bm + _r) * K + _kk + _c * 8;            \
            asm volatile("cp.async.ca.shared.global [%0], [%1], 16;"           \
                         :: "r"(_d), "l"(Ahi + _o));                           \
            asm volatile("cp.async.ca.shared.global [%0], [%1], 16;"           \
                         :: "r"(_d + AT), "l"(Alo + _o));                      \
        }                                                                      \
        _Pragma("unroll")                                                      \
        for (int _i = 0; _i < BCH; _i++) {                                     \
            const int _u = tid + _i * 256;                                     \
            const int _r = _u >> 2, _c = _u & 3;                               \
            const uint32_t _d = _sb + 2 * AT + _r * 64 +                       \
                                ((_c ^ ((_r >> 1) & 3)) << 4);                 \
            const size_t _o = (size_t)(bn + _r) * K + _kk + _c * 8;            \
            asm volatile("cp.async.ca.shared.global [%0], [%1], 16;"           \
                         :: "r"(_d), "l"(Bhi + _o));                           \
            asm volatile("cp.async.ca.shared.global [%0], [%1], 16;"           \
                         :: "r"(_d + BT), "l"(Blo + _o));                      \
        }                                                                      \
    }

#pragma unroll
    for (int i = 0; i < S - 1; i++) {
        PREFETCH(i);
        asm volatile("cp.async.commit_group;" ::: "memory");
    }

    for (int c = 0; c < NCH; c++) {
        asm volatile("cp.async.wait_group %0;" :: "n"(S - 2) : "memory");
        __syncthreads();

        if (c + S - 1 < NCH) PREFETCH(c + S - 1);
        asm volatile("cp.async.commit_group;" ::: "memory");

        const uint32_t sb = sbase + (c % S) * STAGE;

#pragma unroll
        for (int ks = 0; ks < 2; ks++) {
            const uint32_t coff = (uint32_t)(((ks * 2 + chi) ^ sx) << 4);
            const uint32_t aBh = sb + (uint32_t)(wm * WM + lrow) * 64 + coff;
            const uint32_t bBh = sb + 2 * AT + (uint32_t)(wn * WN + lrow) * 64 + coff;

            uint32_t ah[MT][4], al[MT][4], bh[NT][2], bl[NT][2];
#pragma unroll
            for (int mt = 0; mt < MT; mt++) {
                ldsm_x4(aBh + mt * 16 * 64, ah[mt]);
                ldsm_x4(aBh + AT + mt * 16 * 64, al[mt]);
            }
#pragma unroll
            for (int p = 0; p < NP; p++) {
                uint32_t r[4];
                ldsm_x4(bBh + p * 16 * 64, r);
                bh[2 * p + 0][0] = r[0]; bh[2 * p + 1][0] = r[1];
                bh[2 * p + 0][1] = r[2]; bh[2 * p + 1][1] = r[3];
                ldsm_x4(bBh + BT + p * 16 * 64, r);
                bl[2 * p + 0][0] = r[0]; bl[2 * p + 1][0] = r[1];
                bl[2 * p + 0][1] = r[2]; bl[2 * p + 1][1] = r[3];
            }
#pragma unroll
            for (int mt = 0; mt < MT; mt++)
#pragma unroll
                for (int nt = 0; nt < NT; nt++)
                    mma_bf16(acc[mt][nt], ah[mt], bh[nt]);
#pragma unroll
            for (int mt = 0; mt < MT; mt++)
#pragma unroll
                for (int nt = 0; nt < NT; nt++)
                    mma_bf16(acc[mt][nt], al[mt], bh[nt]);
#pragma unroll
            for (int mt = 0; mt < MT; mt++)
#pragma unroll
                for (int nt = 0; nt < NT; nt++)
                    mma_bf16(acc[mt][nt], ah[mt], bl[nt]);
        }
    }
#undef PREFETCH

#pragma unroll
    for (int mt = 0; mt < MT; mt++) {
#pragma unroll
        for (int nt = 0; nt < NT; nt++) {
            const int m = bm + wm * WM + mt * 16 + gid;
            const int n = bn + wn * WN + nt * 8 + 2 * tig;
            float b0 = bias ? bias[n] : 0.0f;
            float b1 = bias ? bias[n + 1] : 0.0f;
            float2 v0 = make_float2(acc[mt][nt][0] + b0, acc[mt][nt][1] + b1);
            float2 v1 = make_float2(acc[mt][nt][2] + b0, acc[mt][nt][3] + b1);
            *reinterpret_cast<float2*>(&C[(size_t)m * N + n]) = v0;
            *reinterpret_cast<float2*>(&C[(size_t)(m + 8) * N + n]) = v1;
        }
    }
}

// ---------------------------------------------------------------------------
// Attention v6: block = query, 16 warps; warp (h, sub) handles head h with
// sub in {0,1} splitting the compacted neighbor list (interleaved halves).
// ---------------------------------------------------------------------------
__device__ __forceinline__ float warpSum(float v) {
#pragma unroll
    for (int o = 16; o > 0; o >>= 1) v += __shfl_xor_sync(0xffffffffu, v, o);
    return v;
}
__device__ __forceinline__ float warpMax(float v) {
#pragma unroll
    for (int o = 16; o > 0; o >>= 1) v = fmaxf(v, __shfl_xor_sync(0xffffffffu, v, o));
    return v;
}

__device__ __forceinline__ void pack_hilo(float4 v, uint2& hi, uint2& lo) {
    unsigned short h[4], l[4];
    float vv[4] = {v.x, v.y, v.z, v.w};
#pragma unroll
    for (int j = 0; j < 4; j++) {
        __nv_bfloat16 hb = __float2bfloat16_rn(vv[j]);
        h[j] = __bfloat16_as_ushort(hb);
        l[j] = __bfloat16_as_ushort(__float2bfloat16_rn(vv[j] - __bfloat162float(hb)));
    }
    hi = make_uint2((uint32_t)h[0] | ((uint32_t)h[1] << 16),
                    (uint32_t)h[2] | ((uint32_t)h[3] << 16));
    lo = make_uint2((uint32_t)l[0] | ((uint32_t)l[1] << 16),
                    (uint32_t)l[2] | ((uint32_t)l[3] << 16));
}

__global__ void __launch_bounds__(512)
attn_kernel(const float* __restrict__ qkv, const int* __restrict__ nbr,
            const int* __restrict__ cnt,
            __nv_bfloat16* __restrict__ ahi, __nv_bfloat16* __restrict__ alo) {
    __shared__ float sims[HEADS][128];
    __shared__ float4 part4[HEADS][16];   // sub=1 partial PV outputs

    const int bid = blockIdx.x;
    const int tid = threadIdx.x;

    if (bid == 2047) {
        const int c = tid;   // 512 threads cover 512 cols
        float v = qkv[2 * INNER + c];
        __nv_bfloat16 hb = __float2bfloat16_rn(v);
        ahi[c] = hb;
        alo[c] = __float2bfloat16_rn(v - __bfloat162float(hb));
        return;
    }

    const int qi   = bid;
    const int wid  = tid >> 5;
    const int sub  = wid & 1;           // list half
    const int h    = wid >> 1;          // head
    const int lane = tid & 31;
    const int g    = lane >> 3;
    const int li   = lane & 7;

    const float* qrow = qkv + (size_t)(qi + 1) * QKVW + h * DHEAD;
    float4 q4a = *reinterpret_cast<const float4*>(qrow + li * 4);
    float4 q4b = *reinterpret_cast<const float4*>(qrow + 32 + li * 4);
    const float sc = 0.125f;
    q4a.x *= sc; q4a.y *= sc; q4a.z *= sc; q4a.w *= sc;
    q4b.x *= sc; q4b.y *= sc; q4b.z *= sc; q4b.w *= sc;

    const float* kbase = qkv + INNER;
    const float* vbase = qkv + 2 * INNER;

    const int n = cnt[qi];
    const int* list = nbr + qi * 128;

    // ---- QK over this warp's interleaved half ----
    for (int j0 = sub * 4; j0 < n; j0 += 8) {
        const int j = j0 + g;
        const bool act = j < n;
        float part = 0.0f;
        if (act) {
            const int row = __ldg(list + j);
            const float* kr = kbase + (size_t)row * QKVW + h * DHEAD;
            float4 k4a = *reinterpret_cast<const float4*>(kr + li * 4);
            float4 k4b = *reinterpret_cast<const float4*>(kr + 32 + li * 4);
            part = q4a.x * k4a.x + q4a.y * k4a.y + q4a.z * k4a.z + q4a.w * k4a.w +
                   q4b.x * k4b.x + q4b.y * k4b.y + q4b.z * k4b.z + q4b.w * k4b.w;
        }
        part += __shfl_xor_sync(0xffffffffu, part, 1);
        part += __shfl_xor_sync(0xffffffffu, part, 2);
        part += __shfl_xor_sync(0xffffffffu, part, 4);
        if (act && li == 0) sims[h][j] = part;
    }
    __syncthreads();

    // ---- softmax (computed redundantly by both warps of the pair) ----
    float sv[4];
#pragma unroll
    for (int t = 0; t < 4; t++) {
        const int j = lane + 32 * t;
        sv[t] = (j < n) ? sims[h][j] : -FLT_MAX;
    }
    float m = fmaxf(fmaxf(sv[0], sv[1]), fmaxf(sv[2], sv[3]));
    m = warpMax(m);
    float z = 0.0f;
#pragma unroll
    for (int t = 0; t < 4; t++) {
        sv[t] = __expf(sv[t] - m);
        z += sv[t];
    }
    z = warpSum(z);
    const float invz = 1.0f / z;
    __syncthreads();      // all reads of raw sims done before overwrite
    if (sub == 0) {
#pragma unroll
        for (int t = 0; t < 4; t++) {
            const int j = lane + 32 * t;
            if (j < n) sims[h][j] = sv[t] * invz;
        }
    }
    __syncthreads();

    // ---- PV over this warp's half ----
    float4 aa = make_float4(0.f, 0.f, 0.f, 0.f);
    float4 ab = make_float4(0.f, 0.f, 0.f, 0.f);
    for (int j0 = sub * 4; j0 < n; j0 += 8) {
        const int j = j0 + g;
        if (j < n) {
            const float p = sims[h][j];
            const int row = __ldg(list + j);
            const float* vr = vbase + (size_t)row * QKVW + h * DHEAD;
            float4 v4a = *reinterpret_cast<const float4*>(vr + li * 4);
            float4 v4b = *reinterpret_cast<const float4*>(vr + 32 + li * 4);
            aa.x = fmaf(p, v4a.x, aa.x); aa.y = fmaf(p, v4a.y, aa.y);
            aa.z = fmaf(p, v4a.z, aa.z); aa.w = fmaf(p, v4a.w, aa.w);
            ab.x = fmaf(p, v4b.x, ab.x); ab.y = fmaf(p, v4b.y, ab.y);
            ab.z = fmaf(p, v4b.z, ab.z); ab.w = fmaf(p, v4b.w, ab.w);
        }
    }

#pragma unroll
    for (int off = 8; off <= 16; off <<= 1) {
        aa.x += __shfl_xor_sync(0xffffffffu, aa.x, off);
        aa.y += __shfl_xor_sync(0xffffffffu, aa.y, off);
        aa.z += __shfl_xor_sync(0xffffffffu, aa.z, off);
        aa.w += __shfl_xor_sync(0xffffffffu, aa.w, off);
        ab.x += __shfl_xor_sync(0xffffffffu, ab.x, off);
        ab.y += __shfl_xor_sync(0xffffffffu, ab.y, off);
        ab.z += __shfl_xor_sync(0xffffffffu, ab.z, off);
        ab.w += __shfl_xor_sync(0xffffffffu, ab.w, off);
    }

    if (sub == 1 && g == 0) {
        part4[h][li] = aa;
        part4[h][8 + li] = ab;
    }
    __syncthreads();

    if (sub == 0 && g == 0) {
        const float4 pa = part4[h][li];
        const float4 pb = part4[h][8 + li];
        aa.x += pa.x; aa.y += pa.y; aa.z += pa.z; aa.w += pa.w;
        ab.x += pb.x; ab.y += pb.y; ab.z += pb.z; ab.w += pb.w;

        const size_t obase = (size_t)(qi + 1) * INNER + h * DHEAD;
        uint2 hi, lo;
        pack_hilo(aa, hi, lo);
        *reinterpret_cast<uint2*>(ahi + obase + li * 4) = hi;
        *reinterpret_cast<uint2*>(alo + obase + li * 4) = lo;
        pack_hilo(ab, hi, lo);
        *reinterpret_cast<uint2*>(ahi + obase + 32 + li * 4) = hi;
        *reinterpret_cast<uint2*>(alo + obase + 32 + li * 4) = lo;
    }
}

// ---------------------------------------------------------------------------
extern "C" void kernel_launch(void* const* d_in, const int* in_sizes, int n_in,
                              void* d_out, int out_size) {
    const float* x     = (const float*)d_in[0];  // (1, 2048, 512)
    const float* w_qkv = (const float*)d_in[1];  // (512, 1536)
    const float* w_out = (const float*)d_in[2];  // (512, 512)
    const float* b_out = (const float*)d_in[3];  // (512,)
    float* out = (float*)d_out;

    float* qkv;
    int *nbr, *cnt;
    __nv_bfloat16 *xhi, *xlo, *w1hiT, *w1loT, *ahi, *alo, *w2hiT, *w2loT;
    cudaGetSymbolAddress((void**)&qkv,   g_qkv);
    cudaGetSymbolAddress((void**)&nbr,   g_nbr);
    cudaGetSymbolAddress((void**)&cnt,   g_cnt);
    cudaGetSymbolAddress((void**)&xhi,   g_xhi);
    cudaGetSymbolAddress((void**)&xlo,   g_xlo);
    cudaGetSymbolAddress((void**)&w1hiT, g_w1hiT);
    cudaGetSymbolAddress((void**)&w1loT, g_w1loT);
    cudaGetSymbolAddress((void**)&ahi,   g_ahi);
    cudaGetSymbolAddress((void**)&alo,   g_alo);
    cudaGetSymbolAddress((void**)&w2hiT, g_w2hiT);
    cudaGetSymbolAddress((void**)&w2loT, g_w2loT);

    const int smem1 = 3 * (2 * 64 * 64 + 2 * 128 * 64);   // 73728, BM=64 BN=128, S=3
    const int smem2 = 4 * (2 * 64 * 64 + 2 * 64 * 64);    // 65536, BM=BN=64,  S=4
    cudaFuncSetAttribute((const void*)gemm_so_kernel<64, 128, 3, 3>,
                         cudaFuncAttributeMaxDynamicSharedMemorySize, smem1);
    cudaFuncSetAttribute((const void*)gemm_so_kernel<64, 64, 4, 3>,
                         cudaFuncAttributeMaxDynamicSharedMemorySize, smem2);

    // 0) fused prep + neighbor lists
    prep_kernel<<<2048, 256>>>(x, w_qkv, w_out, xhi, xlo, w1hiT, w1loT,
                               w2hiT, w2loT);
    nbr_kernel<<<256, 256>>>(nbr, cnt);

    // 1) qkv = x @ w_qkv   (R13 config: 64x128 tiles, S=3, 3 CTAs/SM)
    gemm_so_kernel<64, 128, 3, 3><<<dim3(QKVW / 128, NTOK / 64), 256, smem1>>>(
        xhi, xlo, w1hiT, w1loT, qkv, nullptr, QKVW);

    // 2) windowed causal attention, warp-pair split per (query, head)
    attn_kernel<<<2048, 512>>>(qkv, nbr, cnt, ahi, alo);

    // 3) out = attn @ w_out + b_out
    gemm_so_kernel<64, 64, 4, 3><<<dim3(INNER / 64, NTOK / 64), 256, smem2>>>(
        ahi, alo, w2hiT, w2loT, out, b_out, INNER);
}

// round 16
// speedup vs baseline: 1.0944x; 1.0944x over previous
#include <cuda_runtime.h>
#include <cuda_bf16.h>
#include <cstdint>
#include <float.h>
#include <math.h>

// Problem constants
#define NTOK   2048          // N = F*H*W = 2*32*32
#define INNER  512
#define QKVW   1536          // 3*INNER
#define HEADS  8
#define DHEAD  64
#define KDIM   512           // GEMM K for both GEMMs

// Scratch (device globals; no allocation allowed)
__device__ float g_qkv[NTOK * QKVW];
__device__ __nv_bfloat16 g_xhi[NTOK * INNER],    g_xlo[NTOK * INNER];
__device__ __nv_bfloat16 g_w1hiT[QKVW * INNER],  g_w1loT[QKVW * INNER];   // [N,K]
__device__ __nv_bfloat16 g_ahi[NTOK * INNER],    g_alo[NTOK * INNER];
__device__ __nv_bfloat16 g_w2hiT[INNER * INNER], g_w2loT[INNER * INNER];  // [N,K]
__device__ int g_nbr[NTOK * 128];   // compacted valid window rows per query
__device__ int g_cnt[NTOK];         // valid count per query

// ---------------------------------------------------------------------------
// Fused prep: split x + transpose-split weights + neighbor lists.
// Blocks: [0,1024) x-split, [1024,1792) w1, [1792,2048) w2, [2048,2304) nbr.
// ---------------------------------------------------------------------------
__device__ __forceinline__ void split_quad(const float* __restrict__ in,
                                           __nv_bfloat16* __restrict__ hi,
                                           __nv_bfloat16* __restrict__ lo,
                                           int base) {
    float4 v = *reinterpret_cast<const float4*>(in + base);
    float vv[4] = {v.x, v.y, v.z, v.w};
    unsigned short h[4], l[4];
#pragma unroll
    for (int j = 0; j < 4; j++) {
        __nv_bfloat16 hb = __float2bfloat16_rn(vv[j]);
        h[j] = __bfloat16_as_ushort(hb);
        l[j] = __bfloat16_as_ushort(__float2bfloat16_rn(vv[j] - __bfloat162float(hb)));
    }
    uint2 ho = make_uint2((uint32_t)h[0] | ((uint32_t)h[1] << 16),
                          (uint32_t)h[2] | ((uint32_t)h[3] << 16));
    uint2 lz = make_uint2((uint32_t)l[0] | ((uint32_t)l[1] << 16),
                          (uint32_t)l[2] | ((uint32_t)l[3] << 16));
    *reinterpret_cast<uint2*>(hi + base) = ho;
    *reinterpret_cast<uint2*>(lo + base) = lz;
}

__device__ __forceinline__ void tsplit_tile(const float* __restrict__ in,
                                            __nv_bfloat16* __restrict__ hiT,
                                            __nv_bfloat16* __restrict__ loT,
                                            int K, int N, int n0, int k0,
                                            float (*sm)[33]) {
    const int tx = threadIdx.x & 31, ty = threadIdx.x >> 5;
#pragma unroll
    for (int i = 0; i < 4; i++)
        sm[ty + i * 8][tx] = in[(size_t)(k0 + ty + i * 8) * N + n0 + tx];
    __syncthreads();
#pragma unroll
    for (int i = 0; i < 4; i++) {
        int nr = ty + i * 8;
        float v = sm[tx][nr];
        __nv_bfloat16 hb = __float2bfloat16_rn(v);
        hiT[(size_t)(n0 + nr) * K + k0 + tx] = hb;
        loT[(size_t)(n0 + nr) * K + k0 + tx] =
            __float2bfloat16_rn(v - __bfloat162float(hb));
    }
}

__device__ __forceinline__ void build_nbr(int qi, int lane,
                                          int* __restrict__ nbr,
                                          int* __restrict__ cnt) {
    if (qi >= 2047) {
        if (qi == 2047 && lane == 0) cnt[qi] = 0;
        return;
    }
    const int f  = qi >> 10;
    const int yy = (qi >> 5) & 31;
    const int xx = qi & 31;
    int base = 0;
#pragma unroll
    for (int t = 0; t < 4; t++) {
        const int s = t * 32 + lane;   // slot 0 = BOS, 1..125 = stencil
        bool valid = false;
        int row = 0;
        if (s == 0) {
            valid = true;
        } else if (s <= 125) {
            const int jj = s - 1;
            const int df = jj / 25;
            const int rem = jj - df * 25;
            const int dh = rem / 5;
            const int dw = rem - dh * 5;
            const int nf = f + df - 2, nh = yy + dh - 2, nw = xx + dw - 2;
            const int nidx = (nf << 10) + (nh << 5) + nw;
            valid = ((unsigned)nf < 2u) && ((unsigned)nh < 32u) &&
                    ((unsigned)nw < 32u) && (nidx <= qi);
            row = nidx + 1;
        }
        const unsigned mask = __ballot_sync(0xffffffffu, valid);
        const int pos = base + __popc(mask & ((1u << lane) - 1u));
        if (valid) nbr[qi * 128 + pos] = row;
        base += __popc(mask);
    }
    if (lane == 0) cnt[qi] = base;
}

__global__ void __launch_bounds__(256)
prep_kernel(const float* __restrict__ x, const float* __restrict__ w1,
            const float* __restrict__ w2,
            __nv_bfloat16* __restrict__ xhi, __nv_bfloat16* __restrict__ xlo,
            __nv_bfloat16* __restrict__ w1hiT, __nv_bfloat16* __restrict__ w1loT,
            __nv_bfloat16* __restrict__ w2hiT, __nv_bfloat16* __restrict__ w2loT,
            int* __restrict__ nbr, int* __restrict__ cnt) {
    __shared__ float sm[32][33];
    const int b = blockIdx.x;
    if (b < 1024) {
        split_quad(x, xhi, xlo, (b * 256 + threadIdx.x) * 4);
    } else if (b < 1024 + 768) {
        const int bx = b - 1024;                   // 48 x 16 tiles
        tsplit_tile(w1, w1hiT, w1loT, KDIM, QKVW,
                    (bx % 48) * 32, (bx / 48) * 32, sm);
    } else if (b < 2048) {
        const int bx = b - 1792;                   // 16 x 16 tiles
        tsplit_tile(w2, w2hiT, w2loT, KDIM, INNER,
                    (bx % 16) * 32, (bx / 16) * 32, sm);
    } else {
        const int qi = (b - 2048) * 8 + (threadIdx.x >> 5);
        build_nbr(qi, threadIdx.x & 31, nbr, cnt);
    }
}

// ---------------------------------------------------------------------------
// bf16x3 shared-operand GEMM (R13 config), templated block tile.
// ---------------------------------------------------------------------------
__device__ __forceinline__ void mma_bf16(float* c, const uint32_t* a, const uint32_t* b) {
    asm volatile(
        "mma.sync.aligned.m16n8k16.row.col.f32.bf16.bf16.f32 "
        "{%0,%1,%2,%3}, {%4,%5,%6,%7}, {%8,%9}, {%0,%1,%2,%3};\n"
        : "+f"(c[0]), "+f"(c[1]), "+f"(c[2]), "+f"(c[3])
        : "r"(a[0]), "r"(a[1]), "r"(a[2]), "r"(a[3]), "r"(b[0]), "r"(b[1]));
}

__device__ __forceinline__ void ldsm_x4(uint32_t addr, uint32_t* r) {
    asm volatile("ldmatrix.sync.aligned.m8n8.x4.shared.b16 {%0,%1,%2,%3}, [%4];"
                 : "=r"(r[0]), "=r"(r[1]), "=r"(r[2]), "=r"(r[3]) : "r"(addr));
}

__device__ __forceinline__ uint32_t smem_u32(const void* p) {
    uint32_t a;
    asm("{ .reg .u64 t; cvta.to.shared.u64 t, %1; cvt.u32.u64 %0, t; }"
        : "=r"(a) : "l"(p));
    return a;
}

template <int BM, int BN, int S, int MB>
__global__ void __launch_bounds__(256, MB)
gemm_so_kernel(const __nv_bfloat16* __restrict__ Ahi,
               const __nv_bfloat16* __restrict__ Alo,
               const __nv_bfloat16* __restrict__ Bhi,
               const __nv_bfloat16* __restrict__ Blo,
               float* __restrict__ C, const float* __restrict__ bias, int N) {
    constexpr int K = KDIM;
    constexpr int AT = BM * 64;                  // one A tile bytes
    constexpr int BT = BN * 64;                  // one B tile bytes
    constexpr int STAGE = 2 * AT + 2 * BT;       // Ahi|Alo|Bhi|Blo
    constexpr int NCH = K / 32;                  // 16
    constexpr int WM = BM / 2, WN = BN / 4;
    constexpr int MT = WM / 16, NT = WN / 8, NP = NT / 2;
    constexpr int ACH = BM / 64;                 // A 16B-units per thread
    constexpr int BCH = BN / 64;                 // B 16B-units per thread

    extern __shared__ char dsm[];

    const int tid  = threadIdx.x;
    const int lane = tid & 31, wid = tid >> 5;
    const int gid  = lane >> 2, tig = lane & 3;
    const int wm   = wid >> 2,  wn  = wid & 3;
    const int bm   = blockIdx.y * BM, bn = blockIdx.x * BN;
    const uint32_t sbase = smem_u32(dsm);

    const int lrow = lane & 15;
    const int chi  = lane >> 4;
    const int sx   = (lrow >> 1) & 3;

    float acc[MT][NT][4];
#pragma unroll
    for (int i = 0; i < MT; i++)
#pragma unroll
        for (int j = 0; j < NT; j++)
#pragma unroll
            for (int q = 0; q < 4; q++) acc[i][j][q] = 0.0f;

#define PREFETCH(c)                                                            \
    {                                                                          \
        const uint32_t _sb = sbase + ((c) % S) * STAGE;                        \
        const int _kk = (c) * 32;                                              \
        _Pragma("unroll")                                                      \
        for (int _i = 0; _i < ACH; _i++) {                                     \
            const int _u = tid + _i * 256;                                     \
            const int _r = _u >> 2, _c = _u & 3;                               \
            const uint32_t _d = _sb + _r * 64 + ((_c ^ ((_r >> 1) & 3)) << 4); \
            const size_t _o = (size_t)(bm + _r) * K + _kk + _c * 8;            \
            asm volatile("cp.async.ca.shared.global [%0], [%1], 16;"           \
                         :: "r"(_d), "l"(Ahi + _o));                           \
            asm volatile("cp.async.ca.shared.global [%0], [%1], 16;"           \
                         :: "r"(_d + AT), "l"(Alo + _o));                      \
        }                                                                      \
        _Pragma("unroll")                                                      \
        for (int _i = 0; _i < BCH; _i++) {                                     \
            const int _u = tid + _i * 256;                                     \
            const int _r = _u >> 2, _c = _u & 3;                               \
            const uint32_t _d = _sb + 2 * AT + _r * 64 +                       \
                                ((_c ^ ((_r >> 1) & 3)) << 4);                 \
            const size_t _o = (size_t)(bn + _r) * K + _kk + _c * 8;            \
            asm volatile("cp.async.ca.shared.global [%0], [%1], 16;"           \
                         :: "r"(_d), "l"(Bhi + _o));                           \
            asm volatile("cp.async.ca.shared.global [%0], [%1], 16;"           \
                         :: "r"(_d + BT), "l"(Blo + _o));                      \
        }                                                                      \
    }

#pragma unroll
    for (int i = 0; i < S - 1; i++) {
        PREFETCH(i);
        asm volatile("cp.async.commit_group;" ::: "memory");
    }

    for (int c = 0; c < NCH; c++) {
        asm volatile("cp.async.wait_group %0;" :: "n"(S - 2) : "memory");
        __syncthreads();

        if (c + S - 1 < NCH) PREFETCH(c + S - 1);
        asm volatile("cp.async.commit_group;" ::: "memory");

        const uint32_t sb = sbase + (c % S) * STAGE;

#pragma unroll
        for (int ks = 0; ks < 2; ks++) {
            const uint32_t coff = (uint32_t)(((ks * 2 + chi) ^ sx) << 4);
            const uint32_t aBh = sb + (uint32_t)(wm * WM + lrow) * 64 + coff;
            const uint32_t bBh = sb + 2 * AT + (uint32_t)(wn * WN + lrow) * 64 + coff;

            uint32_t ah[MT][4], al[MT][4], bh[NT][2], bl[NT][2];
#pragma unroll
            for (int mt = 0; mt < MT; mt++) {
                ldsm_x4(aBh + mt * 16 * 64, ah[mt]);
                ldsm_x4(aBh + AT + mt * 16 * 64, al[mt]);
            }
#pragma unroll
            for (int p = 0; p < NP; p++) {
                uint32_t r[4];
                ldsm_x4(bBh + p * 16 * 64, r);
                bh[2 * p + 0][0] = r[0]; bh[2 * p + 1][0] = r[1];
                bh[2 * p + 0][1] = r[2]; bh[2 * p + 1][1] = r[3];
                ldsm_x4(bBh + BT + p * 16 * 64, r);
                bl[2 * p + 0][0] = r[0]; bl[2 * p + 1][0] = r[1];
                bl[2 * p + 0][1] = r[2]; bl[2 * p + 1][1] = r[3];
            }
#pragma unroll
            for (int mt = 0; mt < MT; mt++)
#pragma unroll
                for (int nt = 0; nt < NT; nt++)
                    mma_bf16(acc[mt][nt], ah[mt], bh[nt]);
#pragma unroll
            for (int mt = 0; mt < MT; mt++)
#pragma unroll
                for (int nt = 0; nt < NT; nt++)
                    mma_bf16(acc[mt][nt], al[mt], bh[nt]);
#pragma unroll
            for (int mt = 0; mt < MT; mt++)
#pragma unroll
                for (int nt = 0; nt < NT; nt++)
                    mma_bf16(acc[mt][nt], ah[mt], bl[nt]);
        }
    }
#undef PREFETCH

#pragma unroll
    for (int mt = 0; mt < MT; mt++) {
#pragma unroll
        for (int nt = 0; nt < NT; nt++) {
            const int m = bm + wm * WM + mt * 16 + gid;
            const int n = bn + wn * WN + nt * 8 + 2 * tig;
            float b0 = bias ? bias[n] : 0.0f;
            float b1 = bias ? bias[n + 1] : 0.0f;
            float2 v0 = make_float2(acc[mt][nt][0] + b0, acc[mt][nt][1] + b1);
            float2 v1 = make_float2(acc[mt][nt][2] + b0, acc[mt][nt][3] + b1);
            *reinterpret_cast<float2*>(&C[(size_t)m * N + n]) = v0;
            *reinterpret_cast<float2*>(&C[(size_t)(m + 8) * N + n]) = v1;
        }
    }
}

// ---------------------------------------------------------------------------
// Attention v7: v5 structure (block = query, warp = head, 4 groups of 8),
// compacted neighbor lists, QK/PV loops unrolled x2 for ILP.
// ---------------------------------------------------------------------------
__device__ __forceinline__ float warpSum(float v) {
#pragma unroll
    for (int o = 16; o > 0; o >>= 1) v += __shfl_xor_sync(0xffffffffu, v, o);
    return v;
}
__device__ __forceinline__ float warpMax(float v) {
#pragma unroll
    for (int o = 16; o > 0; o >>= 1) v = fmaxf(v, __shfl_xor_sync(0xffffffffu, v, o));
    return v;
}

__device__ __forceinline__ void pack_hilo(float4 v, uint2& hi, uint2& lo) {
    unsigned short h[4], l[4];
    float vv[4] = {v.x, v.y, v.z, v.w};
#pragma unroll
    for (int j = 0; j < 4; j++) {
        __nv_bfloat16 hb = __float2bfloat16_rn(vv[j]);
        h[j] = __bfloat16_as_ushort(hb);
        l[j] = __bfloat16_as_ushort(__float2bfloat16_rn(vv[j] - __bfloat162float(hb)));
    }
    hi = make_uint2((uint32_t)h[0] | ((uint32_t)h[1] << 16),
                    (uint32_t)h[2] | ((uint32_t)h[3] << 16));
    lo = make_uint2((uint32_t)l[0] | ((uint32_t)l[1] << 16),
                    (uint32_t)l[2] | ((uint32_t)l[3] << 16));
}

__global__ void __launch_bounds__(256)
attn_kernel(const float* __restrict__ qkv, const int* __restrict__ nbr,
            const int* __restrict__ cnt,
            __nv_bfloat16* __restrict__ ahi, __nv_bfloat16* __restrict__ alo) {
    __shared__ float sims[HEADS][128];

    const int bid = blockIdx.x;
    const int tid = threadIdx.x;

    if (bid == 2047) {
        for (int c = tid; c < INNER; c += 256) {
            float v = qkv[2 * INNER + c];
            __nv_bfloat16 hb = __float2bfloat16_rn(v);
            ahi[c] = hb;
            alo[c] = __float2bfloat16_rn(v - __bfloat162float(hb));
        }
        return;
    }

    const int qi   = bid;
    const int h    = tid >> 5;
    const int lane = tid & 31;
    const int g    = lane >> 3;
    const int li   = lane & 7;

    const float* qrow = qkv + (size_t)(qi + 1) * QKVW + h * DHEAD;
    float4 q4a = *reinterpret_cast<const float4*>(qrow + li * 4);
    float4 q4b = *reinterpret_cast<const float4*>(qrow + 32 + li * 4);
    const float sc = 0.125f;
    q4a.x *= sc; q4a.y *= sc; q4a.z *= sc; q4a.w *= sc;
    q4b.x *= sc; q4b.y *= sc; q4b.z *= sc; q4b.w *= sc;

    const float* kbase = qkv + INNER;
    const float* vbase = qkv + 2 * INNER;

    const int n = cnt[qi];                 // warp-uniform (1..126)
    const int* list = nbr + qi * 128;

    // ---- QK phase: two independent slot-chains per iteration ----
    for (int j0 = 0; j0 < n; j0 += 8) {
        const int ja = j0 + g;
        const int jb = j0 + 4 + g;
        const bool actA = ja < n;
        const bool actB = jb < n;
        float pa = 0.0f, pb = 0.0f;
        if (actA) {
            const int row = __ldg(list + ja);
            const float* kr = kbase + (size_t)row * QKVW + h * DHEAD;
            float4 ka = *reinterpret_cast<const float4*>(kr + li * 4);
            float4 kb = *reinterpret_cast<const float4*>(kr + 32 + li * 4);
            pa = q4a.x * ka.x + q4a.y * ka.y + q4a.z * ka.z + q4a.w * ka.w +
                 q4b.x * kb.x + q4b.y * kb.y + q4b.z * kb.z + q4b.w * kb.w;
        }
        if (actB) {
            const int row = __ldg(list + jb);
            const float* kr = kbase + (size_t)row * QKVW + h * DHEAD;
            float4 ka = *reinterpret_cast<const float4*>(kr + li * 4);
            float4 kb = *reinterpret_cast<const float4*>(kr + 32 + li * 4);
            pb = q4a.x * ka.x + q4a.y * ka.y + q4a.z * ka.z + q4a.w * ka.w +
                 q4b.x * kb.x + q4b.y * kb.y + q4b.z * kb.z + q4b.w * kb.w;
        }
        pa += __shfl_xor_sync(0xffffffffu, pa, 1);
        pb += __shfl_xor_sync(0xffffffffu, pb, 1);
        pa += __shfl_xor_sync(0xffffffffu, pa, 2);
        pb += __shfl_xor_sync(0xffffffffu, pb, 2);
        pa += __shfl_xor_sync(0xffffffffu, pa, 4);
        pb += __shfl_xor_sync(0xffffffffu, pb, 4);
        if (actA && li == 0) sims[h][ja] = pa;
        if (actB && li == 0) sims[h][jb] = pb;
    }
    __syncwarp();

    // ---- softmax over n entries (lane owns j = lane + 32t) ----
    float sv[4];
#pragma unroll
    for (int t = 0; t < 4; t++) {
        const int j = lane + 32 * t;
        sv[t] = (j < n) ? sims[h][j] : -FLT_MAX;
    }
    float m = fmaxf(fmaxf(sv[0], sv[1]), fmaxf(sv[2], sv[3]));
    m = warpMax(m);
    float z = 0.0f;
#pragma unroll
    for (int t = 0; t < 4; t++) {
        sv[t] = __expf(sv[t] - m);
        z += sv[t];
    }
    z = warpSum(z);
    const float invz = 1.0f / z;
#pragma unroll
    for (int t = 0; t < 4; t++) {
        const int j = lane + 32 * t;
        if (j < n) sims[h][j] = sv[t] * invz;
    }
    __syncwarp();

    // ---- PV phase: two independent slot-chains per iteration ----
    float4 aa = make_float4(0.f, 0.f, 0.f, 0.f);
    float4 ab = make_float4(0.f, 0.f, 0.f, 0.f);
    float4 ba = make_float4(0.f, 0.f, 0.f, 0.f);
    float4 bb = make_float4(0.f, 0.f, 0.f, 0.f);
    for (int j0 = 0; j0 < n; j0 += 8) {
        const int ja = j0 + g;
        const int jb = j0 + 4 + g;
        if (ja < n) {
            const float p = sims[h][ja];
            const int row = __ldg(list + ja);
            const float* vr = vbase + (size_t)row * QKVW + h * DHEAD;
            float4 va = *reinterpret_cast<const float4*>(vr + li * 4);
            float4 vb = *reinterpret_cast<const float4*>(vr + 32 + li * 4);
            aa.x = fmaf(p, va.x, aa.x); aa.y = fmaf(p, va.y, aa.y);
            aa.z = fmaf(p, va.z, aa.z); aa.w = fmaf(p, va.w, aa.w);
            ab.x = fmaf(p, vb.x, ab.x); ab.y = fmaf(p, vb.y, ab.y);
            ab.z = fmaf(p, vb.z, ab.z); ab.w = fmaf(p, vb.w, ab.w);
        }
        if (jb < n) {
            const float p = sims[h][jb];
            const int row = __ldg(list + jb);
            const float* vr = vbase + (size_t)row * QKVW + h * DHEAD;
            float4 va = *reinterpret_cast<const float4*>(vr + li * 4);
            float4 vb = *reinterpret_cast<const float4*>(vr + 32 + li * 4);
            ba.x = fmaf(p, va.x, ba.x); ba.y = fmaf(p, va.y, ba.y);
            ba.z = fmaf(p, va.z, ba.z); ba.w = fmaf(p, va.w, ba.w);
            bb.x = fmaf(p, vb.x, bb.x); bb.y = fmaf(p, vb.y, bb.y);
            bb.z = fmaf(p, vb.z, bb.z); bb.w = fmaf(p, vb.w, bb.w);
        }
    }
    aa.x += ba.x; aa.y += ba.y; aa.z += ba.z; aa.w += ba.w;
    ab.x += bb.x; ab.y += bb.y; ab.z += bb.z; ab.w += bb.w;

#pragma unroll
    for (int off = 8; off <= 16; off <<= 1) {
        aa.x += __shfl_xor_sync(0xffffffffu, aa.x, off);
        aa.y += __shfl_xor_sync(0xffffffffu, aa.y, off);
        aa.z += __shfl_xor_sync(0xffffffffu, aa.z, off);
        aa.w += __shfl_xor_sync(0xffffffffu, aa.w, off);
        ab.x += __shfl_xor_sync(0xffffffffu, ab.x, off);
        ab.y += __shfl_xor_sync(0xffffffffu, ab.y, off);
        ab.z += __shfl_xor_sync(0xffffffffu, ab.z, off);
        ab.w += __shfl_xor_sync(0xffffffffu, ab.w, off);
    }

    if (g == 0) {
        const size_t obase = (size_t)(qi + 1) * INNER + h * DHEAD;
        uint2 hi, lo;
        pack_hilo(aa, hi, lo);
        *reinterpret_cast<uint2*>(ahi + obase + li * 4) = hi;
        *reinterpret_cast<uint2*>(alo + obase + li * 4) = lo;
        pack_hilo(ab, hi, lo);
        *reinterpret_cast<uint2*>(ahi + obase + 32 + li * 4) = hi;
        *reinterpret_cast<uint2*>(alo + obase + 32 + li * 4) = lo;
    }
}

// ---------------------------------------------------------------------------
extern "C" void kernel_launch(void* const* d_in, const int* in_sizes, int n_in,
                              void* d_out, int out_size) {
    const float* x     = (const float*)d_in[0];  // (1, 2048, 512)
    const float* w_qkv = (const float*)d_in[1];  // (512, 1536)
    const float* w_out = (const float*)d_in[2];  // (512, 512)
    const float* b_out = (const float*)d_in[3];  // (512,)
    float* out = (float*)d_out;

    float* qkv;
    int *nbr, *cnt;
    __nv_bfloat16 *xhi, *xlo, *w1hiT, *w1loT, *ahi, *alo, *w2hiT, *w2loT;
    cudaGetSymbolAddress((void**)&qkv,   g_qkv);
    cudaGetSymbolAddress((void**)&nbr,   g_nbr);
    cudaGetSymbolAddress((void**)&cnt,   g_cnt);
    cudaGetSymbolAddress((void**)&xhi,   g_xhi);
    cudaGetSymbolAddress((void**)&xlo,   g_xlo);
    cudaGetSymbolAddress((void**)&w1hiT, g_w1hiT);
    cudaGetSymbolAddress((void**)&w1loT, g_w1loT);
    cudaGetSymbolAddress((void**)&ahi,   g_ahi);
    cudaGetSymbolAddress((void**)&alo,   g_alo);
    cudaGetSymbolAddress((void**)&w2hiT, g_w2hiT);
    cudaGetSymbolAddress((void**)&w2loT, g_w2loT);

    const int smem1 = 3 * (2 * 64 * 64 + 2 * 128 * 64);   // 73728, BM=64 BN=128, S=3
    const int smem2 = 4 * (2 * 64 * 64 + 2 * 64 * 64);    // 65536, BM=BN=64,  S=4
    cudaFuncSetAttribute((const void*)gemm_so_kernel<64, 128, 3, 3>,
                         cudaFuncAttributeMaxDynamicSharedMemorySize, smem1);
    cudaFuncSetAttribute((const void*)gemm_so_kernel<64, 64, 4, 3>,
                         cudaFuncAttributeMaxDynamicSharedMemorySize, smem2);

    // 0) fused prep (splits + weights + neighbor lists)
    prep_kernel<<<2304, 256>>>(x, w_qkv, w_out, xhi, xlo, w1hiT, w1loT,
                               w2hiT, w2loT, nbr, cnt);

    // 1) qkv = x @ w_qkv   (R13 config)
    gemm_so_kernel<64, 128, 3, 3><<<dim3(QKVW / 128, NTOK / 64), 256, smem1>>>(
        xhi, xlo, w1hiT, w1loT, qkv, nullptr, QKVW);

    // 2) windowed causal attention over compacted lists (ILP x2)
    attn_kernel<<<2048, 256>>>(qkv, nbr, cnt, ahi, alo);

    // 3) out = attn @ w_out + b_out
    gemm_so_kernel<64, 64, 4, 3><<<dim3(INNER / 64, NTOK / 64), 256, smem2>>>(
        ahi, alo, w2hiT, w2loT, out, b_out, INNER);
}